// round 7
// baseline (speedup 1.0000x reference)
#include <cuda_runtime.h>
#include <cstdint>

// Problem constants
#define BB   32
#define SS   64
#define DD   512
#define MM   8192
#define NHD  8
#define HD   64
#define NTOK (BB * SS)          // 2048

// Scratch (device globals per allocation rules)
__device__ float g_Q[NTOK * DD];          // 2048 x 512
__device__ float g_KV[MM * 2 * DD];       // 8192 x 1024   (K cols 0..511, V cols 512..1023)
__device__ float g_AO[NTOK * DD];         // 2048 x 512

// ---------------------------------------------------------------------------
// Generic fp32 GEMM: C[MxN] = A[MxK] * B[NxK]^T + bias[N]
// 64x64 block tile, BK=16, 256 threads, 4x4 register micro-tile.
// smem tiles stored k-major (transposed) so inner loop uses float4 LDS.
// Requires Mrows%64==0, N%64==0, K%16==0 (true for all three calls).
// ---------------------------------------------------------------------------
__global__ __launch_bounds__(256) void gemm_abt(
    const float* __restrict__ A, const float* __restrict__ Bm,
    const float* __restrict__ bias, float* __restrict__ C,
    int K, int N)
{
    __shared__ float As[16 * 64];
    __shared__ float Bs[16 * 64];

    const int tid = threadIdx.x;
    const int tx = tid & 15;       // n micro index
    const int ty = tid >> 4;       // m micro index
    const int bm = blockIdx.y * 64;
    const int bn = blockIdx.x * 64;

    const int lr = tid >> 2;            // 0..63 row within tile for loads
    const int lk = (tid & 3) * 4;       // 0,4,8,12 k offset for loads
    const float* Ab = A  + (size_t)(bm + lr) * K + lk;
    const float* Bb = Bm + (size_t)(bn + lr) * K + lk;

    float acc[4][4];
    #pragma unroll
    for (int i = 0; i < 4; i++)
        #pragma unroll
        for (int j = 0; j < 4; j++) acc[i][j] = 0.f;

    for (int k0 = 0; k0 < K; k0 += 16) {
        float4 a4 = *(const float4*)(Ab + k0);
        float4 b4 = *(const float4*)(Bb + k0);
        As[(lk + 0) * 64 + lr] = a4.x;
        As[(lk + 1) * 64 + lr] = a4.y;
        As[(lk + 2) * 64 + lr] = a4.z;
        As[(lk + 3) * 64 + lr] = a4.w;
        Bs[(lk + 0) * 64 + lr] = b4.x;
        Bs[(lk + 1) * 64 + lr] = b4.y;
        Bs[(lk + 2) * 64 + lr] = b4.z;
        Bs[(lk + 3) * 64 + lr] = b4.w;
        __syncthreads();

        #pragma unroll
        for (int k = 0; k < 16; k++) {
            float4 av = *(const float4*)&As[k * 64 + ty * 4];
            float4 bv = *(const float4*)&Bs[k * 64 + tx * 4];
            float a[4] = {av.x, av.y, av.z, av.w};
            float b[4] = {bv.x, bv.y, bv.z, bv.w};
            #pragma unroll
            for (int i = 0; i < 4; i++)
                #pragma unroll
                for (int j = 0; j < 4; j++)
                    acc[i][j] += a[i] * b[j];
        }
        __syncthreads();
    }

    #pragma unroll
    for (int i = 0; i < 4; i++) {
        int row = bm + ty * 4 + i;
        int col = bn + tx * 4;
        float4 o;
        o.x = acc[i][0] + bias[col + 0];
        o.y = acc[i][1] + bias[col + 1];
        o.z = acc[i][2] + bias[col + 2];
        o.w = acc[i][3] + bias[col + 3];
        *(float4*)&C[(size_t)row * N + col] = o;
    }
}

// ---------------------------------------------------------------------------
// Flash-attention kernel. One block per (b, h). 256 threads.
// Streams M in 64-wide tiles with online softmax. S kept TRANSPOSED in smem
// (St[m][s]) so both inner GEMMs read float4-vectorized, and the softmax
// column reduction is bank-conflict-free.
// Dynamic smem layout (floats):
//   Qt  [64][64]  (k-major, prescaled by 1/8)   @ 0
//   Kt  [64][64]  (k-major)                     @ 4096
//   Vs  [64][64]  (row-major)                   @ 8192
//   St  [64][68]  (pad 68)                      @ 12288
//   mrow[64] lrow[64] crow[64]                  @ 16640/16704/16768
//   red [256]                                   @ 16832
// total 17088 floats = 68352 bytes
// ---------------------------------------------------------------------------
#define ATTN_SMEM_BYTES (17088 * 4)

__global__ __launch_bounds__(256) void attn_kernel()
{
    extern __shared__ float sm[];
    float* Qt   = sm;
    float* Kt   = sm + 4096;
    float* Vs   = sm + 8192;
    float* St   = sm + 12288;
    float* mrow = sm + 16640;
    float* lrow = sm + 16704;
    float* crow = sm + 16768;
    float* red  = sm + 16832;

    const int tid = threadIdx.x;
    const int h = blockIdx.x;
    const int b = blockIdx.y;
    const int tx = tid & 15;
    const int ty = tid >> 4;
    const int sq = tid & 63;      // softmax: column (query) index
    const int part = tid >> 6;    // softmax: 4 partial reducers per column

    // Load Q tile, transposed & prescaled
    #pragma unroll
    for (int p = 0; p < 4; p++) {
        int idx = p * 256 + tid;
        int s = idx >> 4;
        int d4 = (idx & 15) * 4;
        float4 q = *(const float4*)&g_Q[(size_t)(b * 64 + s) * DD + h * HD + d4];
        Qt[(d4 + 0) * 64 + s] = q.x * 0.125f;
        Qt[(d4 + 1) * 64 + s] = q.y * 0.125f;
        Qt[(d4 + 2) * 64 + s] = q.z * 0.125f;
        Qt[(d4 + 3) * 64 + s] = q.w * 0.125f;
    }
    if (tid < 64) { mrow[tid] = -1e30f; lrow[tid] = 0.f; }

    float accO[4][4];
    #pragma unroll
    for (int i = 0; i < 4; i++)
        #pragma unroll
        for (int j = 0; j < 4; j++) accO[i][j] = 0.f;

    for (int t = 0; t < MM / 64; t++) {
        __syncthreads();  // protect Qt (first iter) / St,Vs (later iters) before overwrite

        // Load K tile (transposed) and V tile (row-major)
        #pragma unroll
        for (int p = 0; p < 4; p++) {
            int idx = p * 256 + tid;
            int m = idx >> 4;
            int d4 = (idx & 15) * 4;
            const float* base = &g_KV[(size_t)(t * 64 + m) * (2 * DD) + h * HD + d4];
            float4 kv = *(const float4*)base;
            Kt[(d4 + 0) * 64 + m] = kv.x;
            Kt[(d4 + 1) * 64 + m] = kv.y;
            Kt[(d4 + 2) * 64 + m] = kv.z;
            Kt[(d4 + 3) * 64 + m] = kv.w;
            float4 vv = *(const float4*)(base + DD);
            *(float4*)&Vs[m * 64 + d4] = vv;
        }
        __syncthreads();

        // S GEMM: St[m][s] = sum_d Kt[d][m] * Qt[d][s]
        float accS[4][4];
        #pragma unroll
        for (int i = 0; i < 4; i++)
            #pragma unroll
            for (int j = 0; j < 4; j++) accS[i][j] = 0.f;
        #pragma unroll 8
        for (int d = 0; d < 64; d++) {
            float4 av = *(const float4*)&Kt[d * 64 + ty * 4];
            float4 bv = *(const float4*)&Qt[d * 64 + tx * 4];
            float a[4] = {av.x, av.y, av.z, av.w};
            float bq[4] = {bv.x, bv.y, bv.z, bv.w};
            #pragma unroll
            for (int i = 0; i < 4; i++)
                #pragma unroll
                for (int j = 0; j < 4; j++)
                    accS[i][j] += a[i] * bq[j];
        }
        #pragma unroll
        for (int i = 0; i < 4; i++) {
            float4 o = make_float4(accS[i][0], accS[i][1], accS[i][2], accS[i][3]);
            *(float4*)&St[(ty * 4 + i) * 68 + tx * 4] = o;
        }
        __syncthreads();

        // Online softmax over columns of St (per query s)
        float lm = -1e30f;
        #pragma unroll
        for (int i = 0; i < 16; i++)
            lm = fmaxf(lm, St[(part * 16 + i) * 68 + sq]);
        red[part * 64 + sq] = lm;
        __syncthreads();

        float m_old = mrow[sq];
        float m_new = fmaxf(fmaxf(fmaxf(red[sq], red[64 + sq]),
                                  fmaxf(red[128 + sq], red[192 + sq])), m_old);
        float c = __expf(m_old - m_new);

        float ls = 0.f;
        #pragma unroll
        for (int i = 0; i < 16; i++) {
            float* p = &St[(part * 16 + i) * 68 + sq];
            float e = __expf(*p - m_new);
            *p = e;
            ls += e;
        }
        __syncthreads();                 // all reads of red done before reuse
        red[part * 64 + sq] = ls;
        __syncthreads();
        if (part == 0) {
            lrow[sq] = lrow[sq] * c + (red[sq] + red[64 + sq] + red[128 + sq] + red[192 + sq]);
            mrow[sq] = m_new;
            crow[sq] = c;
        }
        __syncthreads();

        // Rescale accumulator rows by correction factor
        #pragma unroll
        for (int i = 0; i < 4; i++) {
            float f = crow[ty * 4 + i];
            #pragma unroll
            for (int j = 0; j < 4; j++) accO[i][j] *= f;
        }

        // O GEMM: accO[s][d] += sum_m St[m][s] * Vs[m][d]
        #pragma unroll 8
        for (int m = 0; m < 64; m++) {
            float4 av = *(const float4*)&St[m * 68 + ty * 4];
            float4 bv = *(const float4*)&Vs[m * 64 + tx * 4];
            float a[4] = {av.x, av.y, av.z, av.w};
            float vb[4] = {bv.x, bv.y, bv.z, bv.w};
            #pragma unroll
            for (int i = 0; i < 4; i++)
                #pragma unroll
                for (int j = 0; j < 4; j++)
                    accO[i][j] += a[i] * vb[j];
        }
    }

    __syncthreads();
    #pragma unroll
    for (int i = 0; i < 4; i++) {
        int s = ty * 4 + i;
        float inv = 1.f / lrow[s];
        float4 o = make_float4(accO[i][0] * inv, accO[i][1] * inv,
                               accO[i][2] * inv, accO[i][3] * inv);
        *(float4*)&g_AO[(size_t)(b * 64 + s) * DD + h * HD + tx * 4] = o;
    }
}

// ---------------------------------------------------------------------------
// Bank update: new_bank[r] = memory[(r - ptr) mod M] if that index < N else bank[r]
// One block per bank row, 128 threads x float4 = 512 floats.
// ---------------------------------------------------------------------------
__global__ __launch_bounds__(128) void bank_update(
    const float* __restrict__ memory, const float* __restrict__ bank,
    const int* __restrict__ ptrp, float* __restrict__ outbank)
{
    int r = blockIdx.x;
    int ptr = ptrp[0];                        // low 32 bits are correct for i32/i64
    int rel = (r - ptr) % MM;
    if (rel < 0) rel += MM;
    const float* src = (rel < NTOK) ? (memory + (size_t)rel * DD)
                                    : (bank + (size_t)r * DD);
    float4 v = *(const float4*)(src + threadIdx.x * 4);
    *(float4*)(outbank + (size_t)r * DD + threadIdx.x * 4) = v;
}

// ---------------------------------------------------------------------------
// Launch. Inputs (metadata order): query, memory, memory_bank, in_proj_w,
// in_proj_b, out_proj_w, out_proj_b, ptr.
// Output: [retrieved (2048x512) | new_bank (8192x512)] fp32.
// ---------------------------------------------------------------------------
extern "C" void kernel_launch(void* const* d_in, const int* in_sizes, int n_in,
                              void* d_out, int out_size)
{
    const float* query  = (const float*)d_in[0];
    const float* memory = (const float*)d_in[1];
    const float* bank   = (const float*)d_in[2];
    const float* ipw    = (const float*)d_in[3];
    const float* ipb    = (const float*)d_in[4];
    const float* opw    = (const float*)d_in[5];
    const float* opb    = (const float*)d_in[6];
    const int*   ptr    = (const int*)d_in[7];
    float* out = (float*)d_out;

    float *pQ, *pKV, *pAO;
    cudaGetSymbolAddress((void**)&pQ, g_Q);
    cudaGetSymbolAddress((void**)&pKV, g_KV);
    cudaGetSymbolAddress((void**)&pAO, g_AO);

    // 1) Q = query @ Wq^T + bq           [2048 x 512]
    gemm_abt<<<dim3(DD / 64, NTOK / 64), 256>>>(query, ipw, ipb, pQ, DD, DD);

    // 2) K|V = bank @ [Wk;Wv]^T + [bk;bv]  [8192 x 1024]
    gemm_abt<<<dim3(2 * DD / 64, MM / 64), 256>>>(bank, ipw + (size_t)DD * DD,
                                                  ipb + DD, pKV, DD, 2 * DD);

    // 3) Attention (flash, online softmax), writes g_AO [2048 x 512]
    cudaFuncSetAttribute(attn_kernel, cudaFuncAttributeMaxDynamicSharedMemorySize,
                         ATTN_SMEM_BYTES);
    attn_kernel<<<dim3(NHD, BB), 256, ATTN_SMEM_BYTES>>>();

    // 4) retrieved = AO @ out_proj_w^T + b  -> out[0 : 2048*512]
    gemm_abt<<<dim3(DD / 64, NTOK / 64), 256>>>(pAO, opw, opb, out, DD, DD);

    // 5) new_bank -> out[2048*512 : ]
    bank_update<<<MM, 128>>>(memory, bank, ptr, out + (size_t)NTOK * DD);
}

// round 10
// speedup vs baseline: 2.1050x; 2.1050x over previous
#include <cuda_runtime.h>
#include <cuda_bf16.h>
#include <cstdint>

// Problem constants
#define BB   32
#define SS   64
#define DD   512
#define MM   8192
#define NHD  8
#define HD   64
#define NTOK (BB * SS)          // 2048

typedef unsigned short u16;
typedef unsigned int   u32;

// ---------------------------------------------------------------------------
// Scratch (device globals per allocation rules)
// ---------------------------------------------------------------------------
__device__ float g_Q[NTOK * DD];           // 2048 x 512
__device__ float g_KV[MM * 2 * DD];        // 8192 x 1024 (K | V)
__device__ float g_AO[NTOK * DD];          // 2048 x 512
// Pre-split bf16: K row-major [h][m][d], V transposed [h][d][m]
__device__ u16 g_Kh[NHD * MM * HD];
__device__ u16 g_Kl[NHD * MM * HD];
__device__ u16 g_Vth[NHD * HD * MM];
__device__ u16 g_Vtl[NHD * HD * MM];

// ---------------------------------------------------------------------------
// Helpers
// ---------------------------------------------------------------------------
// Pack two fp32 into bf16x2 (lo half = a) and the bf16x2 of the residuals.
__device__ __forceinline__ void split2(float a, float b, u32& hi, u32& lo) {
    asm("cvt.rn.bf16x2.f32 %0, %1, %2;" : "=r"(hi) : "f"(b), "f"(a));
    float ra = a - __uint_as_float(hi << 16);
    float rb = b - __uint_as_float(hi & 0xffff0000u);
    asm("cvt.rn.bf16x2.f32 %0, %1, %2;" : "=r"(lo) : "f"(rb), "f"(ra));
}
__device__ __forceinline__ void split1(float x, u16& h, u16& l) {
    __nv_bfloat16 bh = __float2bfloat16(x);
    float r = x - __bfloat162float(bh);
    __nv_bfloat16 bl = __float2bfloat16(r);
    h = *(u16*)&bh;  l = *(u16*)&bl;
}
// m16n8k16 bf16 MMA, fp32 accumulate in place.
__device__ __forceinline__ void mma16816(float* c, const u32* a, u32 b0, u32 b1) {
    asm volatile(
        "mma.sync.aligned.m16n8k16.row.col.f32.bf16.bf16.f32 "
        "{%0,%1,%2,%3}, {%4,%5,%6,%7}, {%8,%9}, {%0,%1,%2,%3};"
        : "+f"(c[0]), "+f"(c[1]), "+f"(c[2]), "+f"(c[3])
        : "r"(a[0]), "r"(a[1]), "r"(a[2]), "r"(a[3]), "r"(b0), "r"(b1));
}

// ---------------------------------------------------------------------------
// Generic fp32 GEMM: C[MxN] = A[MxK]*B[NxK]^T + bias[N] (projections)
// ---------------------------------------------------------------------------
__global__ __launch_bounds__(256) void gemm_abt(
    const float* __restrict__ A, const float* __restrict__ Bm,
    const float* __restrict__ bias, float* __restrict__ C,
    int K, int N)
{
    __shared__ float As[16 * 64];
    __shared__ float Bs[16 * 64];
    const int tid = threadIdx.x;
    const int tx = tid & 15, ty = tid >> 4;
    const int bm = blockIdx.y * 64, bn = blockIdx.x * 64;
    const int lr = tid >> 2, lk = (tid & 3) * 4;
    const float* Ab = A  + (size_t)(bm + lr) * K + lk;
    const float* Bb = Bm + (size_t)(bn + lr) * K + lk;

    float acc[4][4];
    #pragma unroll
    for (int i = 0; i < 4; i++)
        #pragma unroll
        for (int j = 0; j < 4; j++) acc[i][j] = 0.f;

    for (int k0 = 0; k0 < K; k0 += 16) {
        float4 a4 = *(const float4*)(Ab + k0);
        float4 b4 = *(const float4*)(Bb + k0);
        As[(lk + 0) * 64 + lr] = a4.x; As[(lk + 1) * 64 + lr] = a4.y;
        As[(lk + 2) * 64 + lr] = a4.z; As[(lk + 3) * 64 + lr] = a4.w;
        Bs[(lk + 0) * 64 + lr] = b4.x; Bs[(lk + 1) * 64 + lr] = b4.y;
        Bs[(lk + 2) * 64 + lr] = b4.z; Bs[(lk + 3) * 64 + lr] = b4.w;
        __syncthreads();
        #pragma unroll
        for (int k = 0; k < 16; k++) {
            float4 av = *(const float4*)&As[k * 64 + ty * 4];
            float4 bv = *(const float4*)&Bs[k * 64 + tx * 4];
            float a[4] = {av.x, av.y, av.z, av.w};
            float b[4] = {bv.x, bv.y, bv.z, bv.w};
            #pragma unroll
            for (int i = 0; i < 4; i++)
                #pragma unroll
                for (int j = 0; j < 4; j++)
                    acc[i][j] += a[i] * b[j];
        }
        __syncthreads();
    }
    #pragma unroll
    for (int i = 0; i < 4; i++) {
        int row = bm + ty * 4 + i, col = bn + tx * 4;
        float4 o;
        o.x = acc[i][0] + bias[col + 0]; o.y = acc[i][1] + bias[col + 1];
        o.z = acc[i][2] + bias[col + 2]; o.w = acc[i][3] + bias[col + 3];
        *(float4*)&C[(size_t)row * N + col] = o;
    }
}

// ---------------------------------------------------------------------------
// Split K (row-major bf16 hi/lo) and V (transposed bf16 hi/lo).
// Grid (NHD, MM/64), 256 threads. V staged through smem for coalesced writes.
// ---------------------------------------------------------------------------
__global__ __launch_bounds__(256) void kv_split()
{
    __shared__ float vt[64][65];
    const int h = blockIdx.x, t = blockIdx.y;
    const int m0 = t * 64;
    const int tid = threadIdx.x;

    #pragma unroll
    for (int i = 0; i < 16; i++) {
        int idx = i * 256 + tid;
        int r = idx >> 6, d = idx & 63;
        size_t row = (size_t)(m0 + r) * (2 * DD);
        float kf = g_KV[row + h * HD + d];
        u16 kh, kl; split1(kf, kh, kl);
        size_t ko = ((size_t)h * MM + m0 + r) * HD + d;
        g_Kh[ko] = kh;  g_Kl[ko] = kl;
        vt[r][d] = g_KV[row + DD + h * HD + d];
    }
    __syncthreads();
    #pragma unroll
    for (int i = 0; i < 16; i++) {
        int idx = i * 256 + tid;
        int d = idx >> 6, r = idx & 63;
        u16 vh, vl; split1(vt[r][d], vh, vl);
        size_t vo = ((size_t)h * HD + d) * MM + m0 + r;
        g_Vth[vo] = vh;  g_Vtl[vo] = vl;
    }
}

// ---------------------------------------------------------------------------
// mma.sync flash attention (shift-free softmax, 3-pass bf16 split).
// Grid (NHD, 16 row-blocks of 128 queries), 256 threads = 8 warps.
// Warp w owns query rows q0+16w .. +15. Q A-fragments resident in registers.
// smem tiles padded to 72 elements/row -> conflict-free b-fragment LDS.
// ---------------------------------------------------------------------------
__global__ __launch_bounds__(256) void attn_mma()
{
    __shared__ u16 Kh_s[64][72], Kl_s[64][72];
    __shared__ u16 Vh_s[64][72], Vl_s[64][72];

    const int tid = threadIdx.x, w = tid >> 5, lane = tid & 31;
    const int h = blockIdx.x, bp = blockIdx.y;
    const int gid = lane >> 2, t4 = lane & 3;
    const int q0 = bp * 128 + w * 16;

    // --- Q fragments (load fp32, scale by 1/8, split to hi/lo bf16x2) ---
    u32 qh[4][4], ql[4][4];
    #pragma unroll
    for (int kk = 0; kk < 4; kk++) {
        const float* qb = &g_Q[(size_t)(q0 + gid) * DD + h * HD + 16 * kk + 2 * t4];
        float2 v;
        v = *(const float2*)(qb);                     // (gid, +0)
        split2(v.x * 0.125f, v.y * 0.125f, qh[kk][0], ql[kk][0]);
        v = *(const float2*)(qb + 8 * DD);            // (gid+8, +0)
        split2(v.x * 0.125f, v.y * 0.125f, qh[kk][1], ql[kk][1]);
        v = *(const float2*)(qb + 8);                 // (gid, +8)
        split2(v.x * 0.125f, v.y * 0.125f, qh[kk][2], ql[kk][2]);
        v = *(const float2*)(qb + 8 * DD + 8);        // (gid+8, +8)
        split2(v.x * 0.125f, v.y * 0.125f, qh[kk][3], ql[kk][3]);
    }

    float oacc[8][4];
    #pragma unroll
    for (int j = 0; j < 8; j++)
        #pragma unroll
        for (int i = 0; i < 4; i++) oacc[j][i] = 0.f;
    float ls0 = 0.f, ls1 = 0.f;

    const size_t kbase = ((size_t)h * MM) * HD;          // + (t*64+r)*64
    const size_t vbase = ((size_t)h * HD) * MM;          // + d*8192 + t*64

    for (int t = 0; t < MM / 64; t++) {
        __syncthreads();
        // --- cooperative tile copy: 4 arrays x 512 uint4 ---
        {
            const uint4* srcKh = (const uint4*)(g_Kh + kbase + (size_t)t * 64 * HD);
            const uint4* srcKl = (const uint4*)(g_Kl + kbase + (size_t)t * 64 * HD);
            #pragma unroll
            for (int i = 0; i < 2; i++) {
                int idx = i * 256 + tid;          // 0..511
                int r = idx >> 3, c = idx & 7;
                *(uint4*)&Kh_s[r][c * 8] = srcKh[idx];
                *(uint4*)&Kl_s[r][c * 8] = srcKl[idx];
                // V rows are strided by MM in global (transposed layout)
                const uint4* svh = (const uint4*)(g_Vth + vbase + (size_t)r * MM + t * 64);
                const uint4* svl = (const uint4*)(g_Vtl + vbase + (size_t)r * MM + t * 64);
                *(uint4*)&Vh_s[r][c * 8] = svh[c];
                *(uint4*)&Vl_s[r][c * 8] = svl[c];
            }
        }
        __syncthreads();

        // --- S = Q K^T  (8 n-tiles x 4 k-steps x 3 passes) ---
        float sacc[8][4];
        #pragma unroll
        for (int j = 0; j < 8; j++)
            #pragma unroll
            for (int i = 0; i < 4; i++) sacc[j][i] = 0.f;

        #pragma unroll
        for (int kk = 0; kk < 4; kk++) {
            #pragma unroll
            for (int j = 0; j < 8; j++) {
                int rr = 8 * j + gid, cc = 16 * kk + 2 * t4;
                u32 bh0 = *(const u32*)&Kh_s[rr][cc];
                u32 bh1 = *(const u32*)&Kh_s[rr][cc + 8];
                u32 bl0 = *(const u32*)&Kl_s[rr][cc];
                u32 bl1 = *(const u32*)&Kl_s[rr][cc + 8];
                mma16816(sacc[j], qh[kk], bh0, bh1);
                mma16816(sacc[j], ql[kk], bh0, bh1);
                mma16816(sacc[j], qh[kk], bl0, bl1);
            }
        }

        // --- exp, row-sum, convert to P A-fragments (hi/lo) ---
        u32 ph[4][4], pl[4][4];
        #pragma unroll
        for (int j = 0; j < 8; j++) {
            float e0 = __expf(sacc[j][0]);
            float e1 = __expf(sacc[j][1]);
            float e2 = __expf(sacc[j][2]);
            float e3 = __expf(sacc[j][3]);
            ls0 += e0 + e1;
            ls1 += e2 + e3;
            int kk = j >> 1, sl = (j & 1) * 2;
            split2(e0, e1, ph[kk][sl + 0], pl[kk][sl + 0]);   // rows gid
            split2(e2, e3, ph[kk][sl + 1], pl[kk][sl + 1]);   // rows gid+8
        }

        // --- O += P V  (8 d-tiles x 4 k-steps x 3 passes) ---
        #pragma unroll
        for (int kk = 0; kk < 4; kk++) {
            #pragma unroll
            for (int j = 0; j < 8; j++) {
                int rr = 8 * j + gid, cc = 16 * kk + 2 * t4;
                u32 bh0 = *(const u32*)&Vh_s[rr][cc];
                u32 bh1 = *(const u32*)&Vh_s[rr][cc + 8];
                u32 bl0 = *(const u32*)&Vl_s[rr][cc];
                u32 bl1 = *(const u32*)&Vl_s[rr][cc + 8];
                mma16816(oacc[j], ph[kk], bh0, bh1);
                mma16816(oacc[j], pl[kk], bh0, bh1);
                mma16816(oacc[j], ph[kk], bl0, bl1);
            }
        }
    }

    // --- finalize: quad reduce row sums, normalize, write ---
    ls0 += __shfl_xor_sync(0xffffffffu, ls0, 1);
    ls0 += __shfl_xor_sync(0xffffffffu, ls0, 2);
    ls1 += __shfl_xor_sync(0xffffffffu, ls1, 1);
    ls1 += __shfl_xor_sync(0xffffffffu, ls1, 2);
    float inv0 = 1.f / ls0, inv1 = 1.f / ls1;

    #pragma unroll
    for (int j = 0; j < 8; j++) {
        float* d0 = &g_AO[(size_t)(q0 + gid) * DD + h * HD + 8 * j + 2 * t4];
        *(float2*)d0 = make_float2(oacc[j][0] * inv0, oacc[j][1] * inv0);
        float* d1 = d0 + 8 * DD;
        *(float2*)d1 = make_float2(oacc[j][2] * inv1, oacc[j][3] * inv1);
    }
}

// ---------------------------------------------------------------------------
// Bank update
// ---------------------------------------------------------------------------
__global__ __launch_bounds__(128) void bank_update(
    const float* __restrict__ memory, const float* __restrict__ bank,
    const int* __restrict__ ptrp, float* __restrict__ outbank)
{
    int r = blockIdx.x;
    int ptr = ptrp[0];
    int rel = (r - ptr) % MM;
    if (rel < 0) rel += MM;
    const float* src = (rel < NTOK) ? (memory + (size_t)rel * DD)
                                    : (bank + (size_t)r * DD);
    float4 v = *(const float4*)(src + threadIdx.x * 4);
    *(float4*)(outbank + (size_t)r * DD + threadIdx.x * 4) = v;
}

// ---------------------------------------------------------------------------
// Launch
// ---------------------------------------------------------------------------
extern "C" void kernel_launch(void* const* d_in, const int* in_sizes, int n_in,
                              void* d_out, int out_size)
{
    const float* query  = (const float*)d_in[0];
    const float* memory = (const float*)d_in[1];
    const float* bank   = (const float*)d_in[2];
    const float* ipw    = (const float*)d_in[3];
    const float* ipb    = (const float*)d_in[4];
    const float* opw    = (const float*)d_in[5];
    const float* opb    = (const float*)d_in[6];
    const int*   ptr    = (const int*)d_in[7];
    float* out = (float*)d_out;

    float *pQ, *pKV, *pAO;
    cudaGetSymbolAddress((void**)&pQ, g_Q);
    cudaGetSymbolAddress((void**)&pKV, g_KV);
    cudaGetSymbolAddress((void**)&pAO, g_AO);

    // 1) Q = query @ Wq^T + bq
    gemm_abt<<<dim3(DD / 64, NTOK / 64), 256>>>(query, ipw, ipb, pQ, DD, DD);
    // 2) K|V = bank @ [Wk;Wv]^T + [bk;bv]
    gemm_abt<<<dim3(2 * DD / 64, MM / 64), 256>>>(bank, ipw + (size_t)DD * DD,
                                                  ipb + DD, pKV, DD, 2 * DD);
    // 3) split K / transpose+split V to bf16 hi/lo
    kv_split<<<dim3(NHD, MM / 64), 256>>>();
    // 4) tensor-core (mma.sync) flash attention -> g_AO
    attn_mma<<<dim3(NHD, 16), 256>>>();
    // 5) retrieved = AO @ out_proj^T + b
    gemm_abt<<<dim3(DD / 64, NTOK / 64), 256>>>(pAO, opw, opb, out, DD, DD);
    // 6) new bank
    bank_update<<<MM, 128>>>(memory, bank, ptr, out + (size_t)NTOK * DD);
}

// round 12
// speedup vs baseline: 3.4423x; 1.6353x over previous
#include <cuda_runtime.h>
#include <cuda_bf16.h>
#include <cstdint>

// Problem constants
#define BB   32
#define SS   64
#define DD   512
#define MM   8192
#define NHD  8
#define HD   64
#define NTOK (BB * SS)          // 2048
#define KSPLIT 4

typedef unsigned short u16;
typedef unsigned int   u32;

// ---------------------------------------------------------------------------
// Scratch (device globals per allocation rules)
// ---------------------------------------------------------------------------
__device__ float g_Q[NTOK * DD];           // 2048 x 512
__device__ float g_KV[MM * 2 * DD];        // 8192 x 1024 (K | V)
__device__ float g_AO[NTOK * DD];          // 2048 x 512
// Pre-split bf16: K row-major [h][m][d], V transposed [h][d][m]
__device__ u16 g_Kh[NHD * MM * HD];
__device__ u16 g_Kl[NHD * MM * HD];
__device__ u16 g_Vth[NHD * HD * MM];
__device__ u16 g_Vtl[NHD * HD * MM];
// Split-K attention partials (unnormalized)
__device__ float g_Opart[KSPLIT][NTOK * DD];
__device__ float g_Lpart[KSPLIT][NTOK * NHD];

// ---------------------------------------------------------------------------
// Helpers
// ---------------------------------------------------------------------------
// Pack two fp32 into bf16x2 (lo half = a) and the bf16x2 of the residuals.
__device__ __forceinline__ void split2(float a, float b, u32& hi, u32& lo) {
    asm("cvt.rn.bf16x2.f32 %0, %1, %2;" : "=r"(hi) : "f"(b), "f"(a));
    float ra = a - __uint_as_float(hi << 16);
    float rb = b - __uint_as_float(hi & 0xffff0000u);
    asm("cvt.rn.bf16x2.f32 %0, %1, %2;" : "=r"(lo) : "f"(rb), "f"(ra));
}
__device__ __forceinline__ void split1(float x, u16& h, u16& l) {
    __nv_bfloat16 bh = __float2bfloat16(x);
    float r = x - __bfloat162float(bh);
    __nv_bfloat16 bl = __float2bfloat16(r);
    h = *(u16*)&bh;  l = *(u16*)&bl;
}
// m16n8k16 bf16 MMA, fp32 accumulate in place. NOT volatile: pure register op,
// lets ptxas interleave independent accumulator chains.
__device__ __forceinline__ void mma16816(float* c, const u32* a, u32 b0, u32 b1) {
    asm("mma.sync.aligned.m16n8k16.row.col.f32.bf16.bf16.f32 "
        "{%0,%1,%2,%3}, {%4,%5,%6,%7}, {%8,%9}, {%0,%1,%2,%3};"
        : "+f"(c[0]), "+f"(c[1]), "+f"(c[2]), "+f"(c[3])
        : "r"(a[0]), "r"(a[1]), "r"(a[2]), "r"(a[3]), "r"(b0), "r"(b1));
}

// ---------------------------------------------------------------------------
// Tensor-core projection GEMM: C[MxN] = A[MxK]*W[NxK]^T + bias[N].
// 3-pass bf16 split (hi*hi + lo*hi + hi*lo), fp32 MMA accumulate.
// Grid (N/64, M/128), 256 threads = 8 warps; warp w owns rows 16w..16w+15,
// all 64 cols. Split to bf16 happens in-register during the smem fill.
// Dynamic smem: Ah[128][72], Al[128][72], Wh[64][72], Wl[64][72] u16 = 55296B.
// ---------------------------------------------------------------------------
#define GPROJ_SMEM 55296

__global__ __launch_bounds__(256) void gemm_mma(
    const float* __restrict__ A, const float* __restrict__ W,
    const float* __restrict__ bias, float* __restrict__ C,
    int K, int N)
{
    extern __shared__ u16 sm2[];
    u16* Ah = sm2;                // [128][72]
    u16* Al = sm2 + 9216;
    u16* Wh = sm2 + 18432;        // [64][72]
    u16* Wl = sm2 + 23040;

    const int tid = threadIdx.x, w = tid >> 5, lane = tid & 31;
    const int gid = lane >> 2, t4 = lane & 3;
    const int bm = blockIdx.y * 128, bn = blockIdx.x * 64;

    float acc[8][4];
    #pragma unroll
    for (int j = 0; j < 8; j++)
        #pragma unroll
        for (int i = 0; i < 4; i++) acc[j][i] = 0.f;

    for (int k0 = 0; k0 < K; k0 += 64) {
        __syncthreads();
        // Fill A tile: 128 rows x 32 float2
        #pragma unroll
        for (int i = 0; i < 16; i++) {
            int idx = i * 256 + tid;
            int r = idx >> 5, c2 = idx & 31;
            float2 v = *(const float2*)&A[(size_t)(bm + r) * K + k0 + 2 * c2];
            u32 hi, lo; split2(v.x, v.y, hi, lo);
            *(u32*)&Ah[r * 72 + 2 * c2] = hi;
            *(u32*)&Al[r * 72 + 2 * c2] = lo;
        }
        // Fill W tile: 64 rows x 32 float2
        #pragma unroll
        for (int i = 0; i < 8; i++) {
            int idx = i * 256 + tid;
            int r = idx >> 5, c2 = idx & 31;
            float2 v = *(const float2*)&W[(size_t)(bn + r) * K + k0 + 2 * c2];
            u32 hi, lo; split2(v.x, v.y, hi, lo);
            *(u32*)&Wh[r * 72 + 2 * c2] = hi;
            *(u32*)&Wl[r * 72 + 2 * c2] = lo;
        }
        __syncthreads();

        #pragma unroll
        for (int kk = 0; kk < 4; kk++) {
            int ar = (16 * w + gid) * 72 + 16 * kk + 2 * t4;
            u32 ah[4], al[4];
            ah[0] = *(const u32*)&Ah[ar];
            ah[1] = *(const u32*)&Ah[ar + 8 * 72];
            ah[2] = *(const u32*)&Ah[ar + 8];
            ah[3] = *(const u32*)&Ah[ar + 8 * 72 + 8];
            al[0] = *(const u32*)&Al[ar];
            al[1] = *(const u32*)&Al[ar + 8 * 72];
            al[2] = *(const u32*)&Al[ar + 8];
            al[3] = *(const u32*)&Al[ar + 8 * 72 + 8];
            #pragma unroll
            for (int j = 0; j < 8; j++) {
                int br = (8 * j + gid) * 72 + 16 * kk + 2 * t4;
                u32 bh0 = *(const u32*)&Wh[br];
                u32 bh1 = *(const u32*)&Wh[br + 8];
                u32 bl0 = *(const u32*)&Wl[br];
                u32 bl1 = *(const u32*)&Wl[br + 8];
                mma16816(acc[j], ah, bh0, bh1);
                mma16816(acc[j], al, bh0, bh1);
                mma16816(acc[j], ah, bl0, bl1);
            }
        }
    }

    #pragma unroll
    for (int j = 0; j < 8; j++) {
        int row = bm + 16 * w + gid;
        int col = bn + 8 * j + 2 * t4;
        float2 b2 = *(const float2*)&bias[col];
        *(float2*)&C[(size_t)row * N + col] =
            make_float2(acc[j][0] + b2.x, acc[j][1] + b2.y);
        *(float2*)&C[(size_t)(row + 8) * N + col] =
            make_float2(acc[j][2] + b2.x, acc[j][3] + b2.y);
    }
}

// ---------------------------------------------------------------------------
// Split K (row-major bf16 hi/lo) and V (transposed bf16 hi/lo).
// Grid (NHD, MM/64), 256 threads. V staged through smem for coalesced writes.
// ---------------------------------------------------------------------------
__global__ __launch_bounds__(256) void kv_split()
{
    __shared__ float vt[64][65];
    const int h = blockIdx.x, t = blockIdx.y;
    const int m0 = t * 64;
    const int tid = threadIdx.x;

    #pragma unroll
    for (int i = 0; i < 16; i++) {
        int idx = i * 256 + tid;
        int r = idx >> 6, d = idx & 63;
        size_t row = (size_t)(m0 + r) * (2 * DD);
        float kf = g_KV[row + h * HD + d];
        u16 kh, kl; split1(kf, kh, kl);
        size_t ko = ((size_t)h * MM + m0 + r) * HD + d;
        g_Kh[ko] = kh;  g_Kl[ko] = kl;
        vt[r][d] = g_KV[row + DD + h * HD + d];
    }
    __syncthreads();
    #pragma unroll
    for (int i = 0; i < 16; i++) {
        int idx = i * 256 + tid;
        int d = idx >> 6, r = idx & 63;
        u16 vh, vl; split1(vt[r][d], vh, vl);
        size_t vo = ((size_t)h * HD + d) * MM + m0 + r;
        g_Vth[vo] = vh;  g_Vtl[vo] = vl;
    }
}

// ---------------------------------------------------------------------------
// mma.sync flash attention, split-K over keys (shift-free softmax -> partials
// combine by addition). Grid (NHD, 16 q-blocks, KSPLIT), 256 threads = 8 warps.
// Each CTA handles 32 key-tiles (2048 keys), writes unnormalized O + sum(exp).
// ---------------------------------------------------------------------------
__global__ __launch_bounds__(256, 2) void attn_mma()
{
    __shared__ u16 Kh_s[64][72], Kl_s[64][72];
    __shared__ u16 Vh_s[64][72], Vl_s[64][72];

    const int tid = threadIdx.x, w = tid >> 5, lane = tid & 31;
    const int h = blockIdx.x, bp = blockIdx.y, z = blockIdx.z;
    const int gid = lane >> 2, t4 = lane & 3;
    const int q0 = bp * 128 + w * 16;

    // --- Q fragments (load fp32, scale by 1/8, split to hi/lo bf16x2) ---
    u32 qh[4][4], ql[4][4];
    #pragma unroll
    for (int kk = 0; kk < 4; kk++) {
        const float* qb = &g_Q[(size_t)(q0 + gid) * DD + h * HD + 16 * kk + 2 * t4];
        float2 v;
        v = *(const float2*)(qb);
        split2(v.x * 0.125f, v.y * 0.125f, qh[kk][0], ql[kk][0]);
        v = *(const float2*)(qb + 8 * DD);
        split2(v.x * 0.125f, v.y * 0.125f, qh[kk][1], ql[kk][1]);
        v = *(const float2*)(qb + 8);
        split2(v.x * 0.125f, v.y * 0.125f, qh[kk][2], ql[kk][2]);
        v = *(const float2*)(qb + 8 * DD + 8);
        split2(v.x * 0.125f, v.y * 0.125f, qh[kk][3], ql[kk][3]);
    }

    float oacc[8][4];
    #pragma unroll
    for (int j = 0; j < 8; j++)
        #pragma unroll
        for (int i = 0; i < 4; i++) oacc[j][i] = 0.f;
    float ls0 = 0.f, ls1 = 0.f;

    const size_t kbase = ((size_t)h * MM) * HD;
    const size_t vbase = ((size_t)h * HD) * MM;
    const int t0 = z * (MM / 64 / KSPLIT);           // 32 tiles per split

    for (int t = t0; t < t0 + MM / 64 / KSPLIT; t++) {
        __syncthreads();
        // --- cooperative tile copy: 4 arrays x 512 uint4 ---
        {
            const uint4* srcKh = (const uint4*)(g_Kh + kbase + (size_t)t * 64 * HD);
            const uint4* srcKl = (const uint4*)(g_Kl + kbase + (size_t)t * 64 * HD);
            #pragma unroll
            for (int i = 0; i < 2; i++) {
                int idx = i * 256 + tid;          // 0..511
                int r = idx >> 3, c = idx & 7;
                *(uint4*)&Kh_s[r][c * 8] = srcKh[idx];
                *(uint4*)&Kl_s[r][c * 8] = srcKl[idx];
                const uint4* svh = (const uint4*)(g_Vth + vbase + (size_t)r * MM + t * 64);
                const uint4* svl = (const uint4*)(g_Vtl + vbase + (size_t)r * MM + t * 64);
                *(uint4*)&Vh_s[r][c * 8] = svh[c];
                *(uint4*)&Vl_s[r][c * 8] = svl[c];
            }
        }
        __syncthreads();

        // --- S = Q K^T  (8 n-tiles x 4 k-steps x 3 passes) ---
        float sacc[8][4];
        #pragma unroll
        for (int j = 0; j < 8; j++)
            #pragma unroll
            for (int i = 0; i < 4; i++) sacc[j][i] = 0.f;

        #pragma unroll
        for (int kk = 0; kk < 4; kk++) {
            #pragma unroll
            for (int j = 0; j < 8; j++) {
                int rr = 8 * j + gid, cc = 16 * kk + 2 * t4;
                u32 bh0 = *(const u32*)&Kh_s[rr][cc];
                u32 bh1 = *(const u32*)&Kh_s[rr][cc + 8];
                u32 bl0 = *(const u32*)&Kl_s[rr][cc];
                u32 bl1 = *(const u32*)&Kl_s[rr][cc + 8];
                mma16816(sacc[j], qh[kk], bh0, bh1);
                mma16816(sacc[j], ql[kk], bh0, bh1);
                mma16816(sacc[j], qh[kk], bl0, bl1);
            }
        }

        // --- exp, row-sum, convert to P A-fragments (hi/lo) ---
        u32 ph[4][4], pl[4][4];
        #pragma unroll
        for (int j = 0; j < 8; j++) {
            float e0 = __expf(sacc[j][0]);
            float e1 = __expf(sacc[j][1]);
            float e2 = __expf(sacc[j][2]);
            float e3 = __expf(sacc[j][3]);
            ls0 += e0 + e1;
            ls1 += e2 + e3;
            int kk = j >> 1, sl = (j & 1) * 2;
            split2(e0, e1, ph[kk][sl + 0], pl[kk][sl + 0]);
            split2(e2, e3, ph[kk][sl + 1], pl[kk][sl + 1]);
        }

        // --- O += P V  (8 d-tiles x 4 k-steps x 3 passes) ---
        #pragma unroll
        for (int kk = 0; kk < 4; kk++) {
            #pragma unroll
            for (int j = 0; j < 8; j++) {
                int rr = 8 * j + gid, cc = 16 * kk + 2 * t4;
                u32 bh0 = *(const u32*)&Vh_s[rr][cc];
                u32 bh1 = *(const u32*)&Vh_s[rr][cc + 8];
                u32 bl0 = *(const u32*)&Vl_s[rr][cc];
                u32 bl1 = *(const u32*)&Vl_s[rr][cc + 8];
                mma16816(oacc[j], ph[kk], bh0, bh1);
                mma16816(oacc[j], pl[kk], bh0, bh1);
                mma16816(oacc[j], ph[kk], bl0, bl1);
            }
        }
    }

    // --- finalize: quad-reduce row sums, write unnormalized partials ---
    ls0 += __shfl_xor_sync(0xffffffffu, ls0, 1);
    ls0 += __shfl_xor_sync(0xffffffffu, ls0, 2);
    ls1 += __shfl_xor_sync(0xffffffffu, ls1, 1);
    ls1 += __shfl_xor_sync(0xffffffffu, ls1, 2);
    if (t4 == 0) {
        g_Lpart[z][(q0 + gid) * NHD + h]     = ls0;
        g_Lpart[z][(q0 + gid + 8) * NHD + h] = ls1;
    }
    #pragma unroll
    for (int j = 0; j < 8; j++) {
        float* d0 = &g_Opart[z][(size_t)(q0 + gid) * DD + h * HD + 8 * j + 2 * t4];
        *(float2*)d0 = make_float2(oacc[j][0], oacc[j][1]);
        float* d1 = d0 + 8 * DD;
        *(float2*)d1 = make_float2(oacc[j][2], oacc[j][3]);
    }
}

// ---------------------------------------------------------------------------
// Split-K reduce: g_AO = (sum_z Opart) / (sum_z Lpart). Grid NTOK x 256.
// ---------------------------------------------------------------------------
__global__ __launch_bounds__(256) void attn_reduce()
{
    const int q = blockIdx.x;
    #pragma unroll
    for (int e = 0; e < 2; e++) {
        int d = threadIdx.x + e * 256;
        int h = d >> 6;
        float l = 0.f, o = 0.f;
        #pragma unroll
        for (int s = 0; s < KSPLIT; s++) {
            l += g_Lpart[s][q * NHD + h];
            o += g_Opart[s][(size_t)q * DD + d];
        }
        g_AO[(size_t)q * DD + d] = o / l;
    }
}

// ---------------------------------------------------------------------------
// Bank update
// ---------------------------------------------------------------------------
__global__ __launch_bounds__(128) void bank_update(
    const float* __restrict__ memory, const float* __restrict__ bank,
    const int* __restrict__ ptrp, float* __restrict__ outbank)
{
    int r = blockIdx.x;
    int ptr = ptrp[0];
    int rel = (r - ptr) % MM;
    if (rel < 0) rel += MM;
    const float* src = (rel < NTOK) ? (memory + (size_t)rel * DD)
                                    : (bank + (size_t)r * DD);
    float4 v = *(const float4*)(src + threadIdx.x * 4);
    *(float4*)(outbank + (size_t)r * DD + threadIdx.x * 4) = v;
}

// ---------------------------------------------------------------------------
// Launch
// ---------------------------------------------------------------------------
extern "C" void kernel_launch(void* const* d_in, const int* in_sizes, int n_in,
                              void* d_out, int out_size)
{
    const float* query  = (const float*)d_in[0];
    const float* memory = (const float*)d_in[1];
    const float* bank   = (const float*)d_in[2];
    const float* ipw    = (const float*)d_in[3];
    const float* ipb    = (const float*)d_in[4];
    const float* opw    = (const float*)d_in[5];
    const float* opb    = (const float*)d_in[6];
    const int*   ptr    = (const int*)d_in[7];
    float* out = (float*)d_out;

    float *pQ, *pKV, *pAO;
    cudaGetSymbolAddress((void**)&pQ, g_Q);
    cudaGetSymbolAddress((void**)&pKV, g_KV);
    cudaGetSymbolAddress((void**)&pAO, g_AO);

    cudaFuncSetAttribute(gemm_mma, cudaFuncAttributeMaxDynamicSharedMemorySize,
                         GPROJ_SMEM);

    // 1) Q = query @ Wq^T + bq            [2048 x 512]
    gemm_mma<<<dim3(DD / 64, NTOK / 128), 256, GPROJ_SMEM>>>(
        query, ipw, ipb, pQ, DD, DD);
    // 2) K|V = bank @ [Wk;Wv]^T + [bk;bv] [8192 x 1024]
    gemm_mma<<<dim3(2 * DD / 64, MM / 128), 256, GPROJ_SMEM>>>(
        bank, ipw + (size_t)DD * DD, ipb + DD, pKV, DD, 2 * DD);
    // 3) split K / transpose+split V to bf16 hi/lo
    kv_split<<<dim3(NHD, MM / 64), 256>>>();
    // 4) split-K mma.sync flash attention -> partials
    attn_mma<<<dim3(NHD, 16, KSPLIT), 256>>>();
    // 5) combine partials -> g_AO
    attn_reduce<<<NTOK, 256>>>();
    // 6) retrieved = AO @ out_proj^T + b
    gemm_mma<<<dim3(DD / 64, NTOK / 128), 256, GPROJ_SMEM>>>(
        pAO, opw, opb, out, DD, DD);
    // 7) new bank
    bank_update<<<MM, 128>>>(memory, bank, ptr, out + (size_t)NTOK * DD);
}